// round 2
// baseline (speedup 1.0000x reference)
#include <cuda_runtime.h>
#include <cuda_bf16.h>

#define NN 50000
#define EE 800000
#define DD 128
#define GG 64
#define NEG_SLOPE 0.2f

// ---------------- scratch (static device globals; no allocations) ------------
__device__ float g_h[NN * DD];     // current node features
__device__ float g_hW[NN * DD];    // projected features (h @ W)
__device__ float g_as[NN];         // per-node alpha_src dot
__device__ float g_ad[NN];         // per-node alpha_dst dot
__device__ int   g_off[NN + 1];    // CSR offsets (by destination)
__device__ int   g_cur[NN];        // scatter cursors
__device__ int   g_nbr[EE];        // CSR neighbor (source) list
__device__ int   g_deg[NN];        // in-degree histogram
__device__ float g_pool[GG * DD];  // pooled sums
__device__ float g_cnt[GG];        // nodes per graph

__device__ __forceinline__ float lrelu(float x) {
    return x > 0.f ? x : NEG_SLOPE * x;
}

// packed fp32x2 FMA (SASS FFMA2) — only reachable via PTX
#define FFMA2(d, a, b) \
    asm("fma.rn.f32x2 %0, %1, %2, %0;" : "+l"(d) : "l"(a), "l"(b))

// ---------------- init ----------------
__global__ void k_zero() {
    int i = blockIdx.x * blockDim.x + threadIdx.x;
    if (i < NN) g_deg[i] = 0;
    if (i < GG * DD) g_pool[i] = 0.f;
    if (i < GG) g_cnt[i] = 0.f;
}

// ---------------- CSR build ----------------
__global__ void k_count(const int* __restrict__ dst) {
    int e = blockIdx.x * blockDim.x + threadIdx.x;
    if (e < EE) atomicAdd(&g_deg[dst[e]], 1);
}

// single block, 1024 threads, 49 elements per thread (1024*49 = 50176 >= NN)
__global__ void k_scan() {
    const int PER = 49;
    __shared__ int wsum[32];
    int tid = threadIdx.x;
    int base = tid * PER;

    int s = 0;
#pragma unroll 7
    for (int j = 0; j < PER; j++) {
        int idx = base + j;
        if (idx < NN) s += g_deg[idx];
    }
    // block exclusive scan of per-thread sums
    int x = s;
#pragma unroll
    for (int o = 1; o < 32; o <<= 1) {
        int y = __shfl_up_sync(0xffffffffu, x, o);
        if ((tid & 31) >= o) x += y;
    }
    if ((tid & 31) == 31) wsum[tid >> 5] = x;
    __syncthreads();
    if (tid < 32) {
        int w = wsum[tid];
#pragma unroll
        for (int o = 1; o < 32; o <<= 1) {
            int y = __shfl_up_sync(0xffffffffu, w, o);
            if (tid >= o) w += y;
        }
        wsum[tid] = w;
    }
    __syncthreads();
    int run = x - s + ((tid >= 32) ? wsum[(tid >> 5) - 1] : 0);  // exclusive

#pragma unroll 7
    for (int j = 0; j < PER; j++) {
        int idx = base + j;
        if (idx < NN) {
            g_off[idx] = run;
            g_cur[idx] = run;
            run += g_deg[idx];
        }
    }
    if (tid == 1023) g_off[NN] = run;
}

__global__ void k_fill(const int* __restrict__ src, const int* __restrict__ dst) {
    int e = blockIdx.x * blockDim.x + threadIdx.x;
    if (e < EE) {
        int p = atomicAdd(&g_cur[dst[e]], 1);
        g_nbr[p] = src[e];
    }
}

// ---------------- GEMM (f32x2): C[N,128] = A[N,128] @ W[128,128] (+bias) -----
// Block: 256 threads, tile 64 rows x 128 cols. K processed in 2 chunks of 64.
// Accumulators hold packed (even-k, odd-k) partial sums; combined at the end.
// Smem: Asp[kp][row] = (A[row][2kp], A[row][2kp+1])   (16 KB)
//       Ws2[kp][col] = (W[2kp][col], W[2kp+1][col])   (32 KB)
__global__ void __launch_bounds__(256) k_gemm(
        const float* __restrict__ Aext, int useExt,
        const float* __restrict__ W,
        const float* __restrict__ bias, int addBias, int outToH) {
    __shared__ float2 Asp[32][64];
    __shared__ float2 Ws2[32][128];

    const float* __restrict__ A = useExt ? Aext : g_h;
    float* __restrict__ C = outToH ? g_h : g_hW;

    int tid = threadIdx.x;
    int row0 = blockIdx.x * 64;
    int warp = tid >> 5, lane = tid & 31;
    int warp_row = warp & 3;        // 4 warp rows  (16 rows each)
    int warp_col = warp >> 2;       // 2 warp cols  (64 cols each)
    int lane_r = lane >> 3;         // 4 row groups (4 rows each)
    int lane_c = lane & 7;          // 8 col groups (2 cols x 4 q-slots)

    int trow = warp_row * 16 + lane_r * 4;                // thread's first row (local)
    int tcol = warp_col * 64 + lane_c * 2;                // + q*16, q<4

    unsigned long long acc[4][4][2];                      // [row i][q][col 0/1]
#pragma unroll
    for (int i = 0; i < 4; i++)
#pragma unroll
        for (int q = 0; q < 4; q++) {
            acc[i][q][0] = 0ull;
            acc[i][q][1] = 0ull;
        }

    for (int kb = 0; kb < 2; kb++) {
        __syncthreads();
        // stage A chunk: 64 rows x 64 k-cols -> pair-transposed
        {
#pragma unroll
            for (int t = 0; t < 4; t++) {
                int slot = tid + t * 256;                 // 1024 float4 slots
                int r = slot >> 4;
                int c4 = (slot & 15) << 2;
                int gr = row0 + r;
                float4 v = make_float4(0.f, 0.f, 0.f, 0.f);
                if (gr < NN) v = *(const float4*)&A[gr * DD + kb * 64 + c4];
                Asp[(c4 >> 1) + 0][r] = make_float2(v.x, v.y);
                Asp[(c4 >> 1) + 1][r] = make_float2(v.z, v.w);
            }
        }
        // stage W chunk: 64 k-rows x 128 cols -> (even,odd) interleaved per col
        {
#pragma unroll
            for (int t = 0; t < 8; t++) {
                int slot = tid + t * 256;                 // 2048 float4 slots
                int k = slot >> 5;
                int c4 = (slot & 31) << 2;
                float4 v = *(const float4*)&W[(kb * 64 + k) * DD + c4];
                float* dstp = &Ws2[k >> 1][c4].x + (k & 1);
                dstp[0] = v.x; dstp[2] = v.y; dstp[4] = v.z; dstp[6] = v.w;
            }
        }
        __syncthreads();

#pragma unroll 4
        for (int kp = 0; kp < 32; kp++) {
            unsigned long long a0 = *(const unsigned long long*)&Asp[kp][trow + 0];
            unsigned long long a1 = *(const unsigned long long*)&Asp[kp][trow + 1];
            unsigned long long a2 = *(const unsigned long long*)&Asp[kp][trow + 2];
            unsigned long long a3 = *(const unsigned long long*)&Asp[kp][trow + 3];
#pragma unroll
            for (int q = 0; q < 4; q++) {
                ulonglong2 b = *(const ulonglong2*)&Ws2[kp][tcol + q * 16];
                FFMA2(acc[0][q][0], a0, b.x); FFMA2(acc[0][q][1], a0, b.y);
                FFMA2(acc[1][q][0], a1, b.x); FFMA2(acc[1][q][1], a1, b.y);
                FFMA2(acc[2][q][0], a2, b.x); FFMA2(acc[2][q][1], a2, b.y);
                FFMA2(acc[3][q][0], a3, b.x); FFMA2(acc[3][q][1], a3, b.y);
            }
        }
    }

    // epilogue: combine even/odd halves, add bias, store float2
#pragma unroll
    for (int i = 0; i < 4; i++) {
        int gr = row0 + trow + i;
        if (gr >= NN) continue;
#pragma unroll
        for (int q = 0; q < 4; q++) {
            int col = tcol + q * 16;
            float2 p0 = *(float2*)&acc[i][q][0];
            float2 p1 = *(float2*)&acc[i][q][1];
            float2 o;
            o.x = p0.x + p0.y;
            o.y = p1.x + p1.y;
            if (addBias) {
                o.x += bias[col];
                o.y += bias[col + 1];
            }
            *(float2*)&C[gr * DD + col] = o;
        }
    }
}

// ---------------- per-node attention dots ----------------
__global__ void k_alpha(const float* __restrict__ a_src,
                        const float* __restrict__ a_dst) {
    int node = blockIdx.x * 8 + (threadIdx.x >> 5);
    int lane = threadIdx.x & 31;
    if (node >= NN) return;
    float4 h = *(const float4*)&g_hW[node * DD + lane * 4];
    float4 s = *(const float4*)&a_src[lane * 4];
    float4 d = *(const float4*)&a_dst[lane * 4];
    float ps = h.x * s.x + h.y * s.y + h.z * s.z + h.w * s.w;
    float pd = h.x * d.x + h.y * d.y + h.z * d.z + h.w * d.w;
#pragma unroll
    for (int o = 16; o; o >>= 1) {
        ps += __shfl_xor_sync(0xffffffffu, ps, o);
        pd += __shfl_xor_sync(0xffffffffu, pd, o);
    }
    if (lane == 0) {
        g_as[node] = ps;
        g_ad[node] = pd;
    }
}

// ---------------- GAT aggregation: softmax over incoming edges + self loop --
__global__ void k_agg(const float* __restrict__ bias) {
    int node = blockIdx.x * 8 + (threadIdx.x >> 5);
    int lane = threadIdx.x & 31;
    if (node >= NN) return;

    int beg = g_off[node];
    int end = g_off[node + 1];
    float adi = g_ad[node];
    float eself = lrelu(g_as[node] + adi);

    // pass 1: exact max (incl. self loop)
    float m = eself;
    for (int t = beg + lane; t < end; t += 32) {
        float e = lrelu(g_as[g_nbr[t]] + adi);
        m = fmaxf(m, e);
    }
#pragma unroll
    for (int o = 16; o; o >>= 1)
        m = fmaxf(m, __shfl_xor_sync(0xffffffffu, m, o));

    // pass 2: denominator
    float ssum = 0.f;
    for (int t = beg + lane; t < end; t += 32)
        ssum += __expf(lrelu(g_as[g_nbr[t]] + adi) - m);
#pragma unroll
    for (int o = 16; o; o >>= 1)
        ssum += __shfl_xor_sync(0xffffffffu, ssum, o);
    ssum += __expf(eself - m);
    float inv = __fdividef(1.f, ssum);

    // pass 3: weighted gather (whole warp per neighbor row, float4/lane)
    int c = lane << 2;
    float wself = __expf(eself - m) * inv;
    float4 hv = *(const float4*)&g_hW[node * DD + c];
    float4 acc = make_float4(wself * hv.x, wself * hv.y, wself * hv.z, wself * hv.w);

    for (int t = beg; t < end; t++) {
        int j = g_nbr[t];
        float wj = __expf(lrelu(g_as[j] + adi) - m) * inv;
        float4 v = *(const float4*)&g_hW[j * DD + c];
        acc.x = fmaf(wj, v.x, acc.x);
        acc.y = fmaf(wj, v.y, acc.y);
        acc.z = fmaf(wj, v.z, acc.z);
        acc.w = fmaf(wj, v.w, acc.w);
    }

    float4 bv = *(const float4*)&bias[c];
    acc.x = fmaxf(acc.x + bv.x, 0.f);
    acc.y = fmaxf(acc.y + bv.y, 0.f);
    acc.z = fmaxf(acc.z + bv.z, 0.f);
    acc.w = fmaxf(acc.w + bv.w, 0.f);
    *(float4*)&g_h[node * DD + c] = acc;
}

// ---------------- global mean pool (sums + counts) ----------------
__global__ void k_pool(const int* __restrict__ batch) {
    int node = blockIdx.x * 8 + (threadIdx.x >> 5);
    int lane = threadIdx.x & 31;
    if (node >= NN) return;
    int b = batch[node];
    float4 v = *(const float4*)&g_h[node * DD + lane * 4];
    atomicAdd(&g_pool[b * DD + lane * 4 + 0], v.x);
    atomicAdd(&g_pool[b * DD + lane * 4 + 1], v.y);
    atomicAdd(&g_pool[b * DD + lane * 4 + 2], v.z);
    atomicAdd(&g_pool[b * DD + lane * 4 + 3], v.w);
    if (lane == 0) atomicAdd(&g_cnt[b], 1.f);
}

// ---------------- final linear ----------------
__global__ void k_final(const float* __restrict__ out_w,
                        const float* __restrict__ out_b,
                        float* __restrict__ out) {
    int g = blockIdx.x;
    int t = threadIdx.x;  // 128
    float v = g_pool[g * DD + t] * out_w[t];
    __shared__ float sh[4];
#pragma unroll
    for (int o = 16; o; o >>= 1) v += __shfl_xor_sync(0xffffffffu, v, o);
    if ((t & 31) == 0) sh[t >> 5] = v;
    __syncthreads();
    if (t == 0) {
        float s = sh[0] + sh[1] + sh[2] + sh[3];
        out[g] = s / g_cnt[g] + out_b[0];
    }
}

// ---------------- launch ----------------
extern "C" void kernel_launch(void* const* d_in, const int* in_sizes, int n_in,
                              void* d_out, int out_size) {
    const float* x     = (const float*)d_in[0];
    const int*   ei    = (const int*)d_in[1];
    const int*   batch = (const int*)d_in[2];
    const float* lin_w = (const float*)d_in[3];
    const float* lin_b = (const float*)d_in[4];
    const float* w1    = (const float*)d_in[5];
    const float* as1   = (const float*)d_in[6];
    const float* ad1   = (const float*)d_in[7];
    const float* b1    = (const float*)d_in[8];
    const float* w2    = (const float*)d_in[9];
    const float* as2   = (const float*)d_in[10];
    const float* ad2   = (const float*)d_in[11];
    const float* b2    = (const float*)d_in[12];
    const float* ow    = (const float*)d_in[13];
    const float* ob    = (const float*)d_in[14];
    float* out = (float*)d_out;

    const int* src = ei;        // edge_index[0]
    const int* dst = ei + EE;   // edge_index[1]

    int gemm_blocks = (NN + 63) / 64;
    int node_blocks = (NN + 7) / 8;
    int edge_blocks = (EE + 255) / 256;

    k_zero<<<(NN + 255) / 256, 256>>>();
    k_count<<<edge_blocks, 256>>>(dst);
    k_scan<<<1, 1024>>>();
    k_fill<<<edge_blocks, 256>>>(src, dst);

    // input projection: g_h = x @ lin_w + lin_b
    k_gemm<<<gemm_blocks, 256>>>(x, 1, lin_w, lin_b, 1, 1);

    // GAT layer 1
    k_gemm<<<gemm_blocks, 256>>>(nullptr, 0, w1, nullptr, 0, 0);
    k_alpha<<<node_blocks, 256>>>(as1, ad1);
    k_agg<<<node_blocks, 256>>>(b1);

    // GAT layer 2
    k_gemm<<<gemm_blocks, 256>>>(nullptr, 0, w2, nullptr, 0, 0);
    k_alpha<<<node_blocks, 256>>>(as2, ad2);
    k_agg<<<node_blocks, 256>>>(b2);

    // pooling + output
    k_pool<<<node_blocks, 256>>>(batch);
    k_final<<<GG, 128>>>(ow, ob, out);
}

// round 3
// speedup vs baseline: 1.1435x; 1.1435x over previous
#include <cuda_runtime.h>
#include <cuda_bf16.h>

#define NN 50000
#define EE 800000
#define DD 128
#define GG 64
#define NEG_SLOPE 0.2f

// ---------------- scratch ----------------
__device__ float g_h[NN * DD];
__device__ float g_hW[NN * DD];
__device__ float g_as[NN];
__device__ float g_ad[NN];
__device__ int   g_off[NN + 1];
__device__ int   g_cur[NN];
__device__ int   g_nbr[EE];
__device__ int   g_deg[NN];
__device__ float g_pool[GG * DD];
__device__ float g_cnt[GG];

__device__ __forceinline__ float lrelu(float x) {
    return x > 0.f ? x : NEG_SLOPE * x;
}

// packed fp32x2 FMA (SASS FFMA2)
#define FFMA2(d, a, b) \
    asm("fma.rn.f32x2 %0, %1, %2, %0;" : "+l"(d) : "l"(a), "l"(b))

// ---------------- init ----------------
__global__ void k_zero() {
    int i = blockIdx.x * blockDim.x + threadIdx.x;
    if (i < NN) g_deg[i] = 0;
    if (i < GG * DD) g_pool[i] = 0.f;
    if (i < GG) g_cnt[i] = 0.f;
}

// ---------------- CSR build ----------------
__global__ void k_count(const int* __restrict__ dst) {
    int e = blockIdx.x * blockDim.x + threadIdx.x;
    if (e < EE) atomicAdd(&g_deg[dst[e]], 1);
}

__global__ void k_scan() {
    const int PER = 49;
    __shared__ int wsum[32];
    int tid = threadIdx.x;
    int base = tid * PER;
    int s = 0;
#pragma unroll 7
    for (int j = 0; j < PER; j++) {
        int idx = base + j;
        if (idx < NN) s += g_deg[idx];
    }
    int x = s;
#pragma unroll
    for (int o = 1; o < 32; o <<= 1) {
        int y = __shfl_up_sync(0xffffffffu, x, o);
        if ((tid & 31) >= o) x += y;
    }
    if ((tid & 31) == 31) wsum[tid >> 5] = x;
    __syncthreads();
    if (tid < 32) {
        int w = wsum[tid];
#pragma unroll
        for (int o = 1; o < 32; o <<= 1) {
            int y = __shfl_up_sync(0xffffffffu, w, o);
            if (tid >= o) w += y;
        }
        wsum[tid] = w;
    }
    __syncthreads();
    int run = x - s + ((tid >= 32) ? wsum[(tid >> 5) - 1] : 0);
#pragma unroll 7
    for (int j = 0; j < PER; j++) {
        int idx = base + j;
        if (idx < NN) {
            g_off[idx] = run;
            g_cur[idx] = run;
            run += g_deg[idx];
        }
    }
    if (tid == 1023) g_off[NN] = run;
}

__global__ void k_fill(const int* __restrict__ src, const int* __restrict__ dst) {
    int e = blockIdx.x * blockDim.x + threadIdx.x;
    if (e < EE) {
        int p = atomicAdd(&g_cur[dst[e]], 1);
        g_nbr[p] = src[e];
    }
}

// ---------------- GEMM (FFMA2, col-pair accumulation) ------------------------
// Block 256 threads, tile 64 rows x 128 cols, K in 4 chunks of 32.
// Asq[row][kp] = (a_2kp, a_2kp, a_2kp+1, a_2kp+1)  -> LDS.128 broadcast = 2 splats
// Ws natural [k][c]                                -> LDS.128 = 2 col-pairs
// Optional fused epilogue: attention dots ps/pd (alpha), replacing k_alpha.
__global__ void __launch_bounds__(256) k_gemm(
        const float* __restrict__ Aext, int useExt,
        const float* __restrict__ W,
        const float* __restrict__ bias, int addBias, int outToH,
        const float* __restrict__ a_src, const float* __restrict__ a_dst,
        int doAlpha) {
    __shared__ float4 Asq[64][17];        // ~17.4 KB (padded)
    __shared__ float  Ws[32][128];        // 16 KB

    const float* __restrict__ A = useExt ? Aext : g_h;
    float* __restrict__ C = outToH ? g_h : g_hW;

    int tid = threadIdx.x;
    int row0 = blockIdx.x * 64;
    int warp = tid >> 5, lane = tid & 31;
    int r0 = warp << 3;                   // 8 rows per warp
    int c = lane << 2;                    // 4 cols per lane (2 pairs)

    unsigned long long acc[8][2];
#pragma unroll
    for (int r = 0; r < 8; r++) { acc[r][0] = 0ull; acc[r][1] = 0ull; }

    for (int kb = 0; kb < 4; kb++) {
        __syncthreads();
        // stage W chunk (32 x 128), natural layout
#pragma unroll
        for (int t = 0; t < 4; t++) {
            int slot = tid + t * 256;
            int k = slot >> 5;
            int c4 = (slot & 31) << 2;
            *(float4*)&Ws[k][c4] = *(const float4*)&W[(kb * 32 + k) * DD + c4];
        }
        // stage A chunk (64 rows x 32 k) as duplicated splat quads
#pragma unroll
        for (int t = 0; t < 2; t++) {
            int s = tid + t * 256;
            int row = s >> 3;             // 0..63
            int g4 = s & 7;               // k-quad within chunk
            int gr = row0 + row;
            float4 v = make_float4(0.f, 0.f, 0.f, 0.f);
            if (gr < NN) v = *(const float4*)&A[gr * DD + kb * 32 + g4 * 4];
            Asq[row][g4 * 2 + 0] = make_float4(v.x, v.x, v.y, v.y);
            Asq[row][g4 * 2 + 1] = make_float4(v.z, v.z, v.w, v.w);
        }
        __syncthreads();

#pragma unroll 4
        for (int kp = 0; kp < 16; kp++) {
            ulonglong2 b0 = *(const ulonglong2*)&Ws[2 * kp + 0][c];
            ulonglong2 b1 = *(const ulonglong2*)&Ws[2 * kp + 1][c];
#pragma unroll
            for (int r = 0; r < 8; r++) {
                ulonglong2 a = *(const ulonglong2*)&Asq[r0 + r][kp];
                FFMA2(acc[r][0], a.x, b0.x);
                FFMA2(acc[r][1], a.x, b0.y);
                FFMA2(acc[r][0], a.y, b1.x);
                FFMA2(acc[r][1], a.y, b1.y);
            }
        }
    }

    float4 bv = make_float4(0, 0, 0, 0);
    if (addBias) bv = *(const float4*)&bias[c];
    float4 sv = make_float4(0, 0, 0, 0), dv = sv;
    if (doAlpha) {
        sv = *(const float4*)&a_src[c];
        dv = *(const float4*)&a_dst[c];
    }

#pragma unroll
    for (int r = 0; r < 8; r++) {
        int gr = row0 + r0 + r;
        float2 p0 = *(float2*)&acc[r][0];
        float2 p1 = *(float2*)&acc[r][1];
        float4 o = make_float4(p0.x + bv.x, p0.y + bv.y, p1.x + bv.z, p1.y + bv.w);
        if (gr < NN) *(float4*)&C[gr * DD + c] = o;
        if (doAlpha) {
            float ps = o.x * sv.x + o.y * sv.y + o.z * sv.z + o.w * sv.w;
            float pd = o.x * dv.x + o.y * dv.y + o.z * dv.z + o.w * dv.w;
#pragma unroll
            for (int of = 16; of; of >>= 1) {
                ps += __shfl_xor_sync(0xffffffffu, ps, of);
                pd += __shfl_xor_sync(0xffffffffu, pd, of);
            }
            if (lane == 0 && gr < NN) {
                g_as[gr] = ps;
                g_ad[gr] = pd;
            }
        }
    }
}

// ---------------- GAT aggregation (+ optional fused pooling) ----------------
__global__ void k_agg(const float* __restrict__ bias,
                      const int* __restrict__ batch, int doPool) {
    int node = blockIdx.x * 8 + (threadIdx.x >> 5);
    int lane = threadIdx.x & 31;
    if (node >= NN) return;

    int beg = g_off[node];
    int end = g_off[node + 1];
    float adi = g_ad[node];
    float eself = lrelu(g_as[node] + adi);

    float m = eself;
    for (int t = beg + lane; t < end; t += 32) {
        float e = lrelu(g_as[g_nbr[t]] + adi);
        m = fmaxf(m, e);
    }
#pragma unroll
    for (int o = 16; o; o >>= 1)
        m = fmaxf(m, __shfl_xor_sync(0xffffffffu, m, o));

    float ssum = 0.f;
    for (int t = beg + lane; t < end; t += 32)
        ssum += __expf(lrelu(g_as[g_nbr[t]] + adi) - m);
#pragma unroll
    for (int o = 16; o; o >>= 1)
        ssum += __shfl_xor_sync(0xffffffffu, ssum, o);
    ssum += __expf(eself - m);
    float inv = __fdividef(1.f, ssum);

    int c = lane << 2;
    float wself = __expf(eself - m) * inv;
    float4 hv = *(const float4*)&g_hW[node * DD + c];
    float4 acc = make_float4(wself * hv.x, wself * hv.y, wself * hv.z, wself * hv.w);

    for (int t = beg; t < end; t++) {
        int j = g_nbr[t];
        float wj = __expf(lrelu(g_as[j] + adi) - m) * inv;
        float4 v = *(const float4*)&g_hW[j * DD + c];
        acc.x = fmaf(wj, v.x, acc.x);
        acc.y = fmaf(wj, v.y, acc.y);
        acc.z = fmaf(wj, v.z, acc.z);
        acc.w = fmaf(wj, v.w, acc.w);
    }

    float4 bv = *(const float4*)&bias[c];
    acc.x = fmaxf(acc.x + bv.x, 0.f);
    acc.y = fmaxf(acc.y + bv.y, 0.f);
    acc.z = fmaxf(acc.z + bv.z, 0.f);
    acc.w = fmaxf(acc.w + bv.w, 0.f);
    *(float4*)&g_h[node * DD + c] = acc;

    if (doPool) {
        int b = batch[node];
        atomicAdd(&g_pool[b * DD + c + 0], acc.x);
        atomicAdd(&g_pool[b * DD + c + 1], acc.y);
        atomicAdd(&g_pool[b * DD + c + 2], acc.z);
        atomicAdd(&g_pool[b * DD + c + 3], acc.w);
        if (lane == 0) atomicAdd(&g_cnt[b], 1.f);
    }
}

// ---------------- final linear ----------------
__global__ void k_final(const float* __restrict__ out_w,
                        const float* __restrict__ out_b,
                        float* __restrict__ out) {
    int g = blockIdx.x;
    int t = threadIdx.x;  // 128
    float v = g_pool[g * DD + t] * out_w[t];
    __shared__ float sh[4];
#pragma unroll
    for (int o = 16; o; o >>= 1) v += __shfl_xor_sync(0xffffffffu, v, o);
    if ((t & 31) == 0) sh[t >> 5] = v;
    __syncthreads();
    if (t == 0) {
        float s = sh[0] + sh[1] + sh[2] + sh[3];
        out[g] = s / g_cnt[g] + out_b[0];
    }
}

// ---------------- launch ----------------
extern "C" void kernel_launch(void* const* d_in, const int* in_sizes, int n_in,
                              void* d_out, int out_size) {
    const float* x     = (const float*)d_in[0];
    const int*   ei    = (const int*)d_in[1];
    const int*   batch = (const int*)d_in[2];
    const float* lin_w = (const float*)d_in[3];
    const float* lin_b = (const float*)d_in[4];
    const float* w1    = (const float*)d_in[5];
    const float* as1   = (const float*)d_in[6];
    const float* ad1   = (const float*)d_in[7];
    const float* b1    = (const float*)d_in[8];
    const float* w2    = (const float*)d_in[9];
    const float* as2   = (const float*)d_in[10];
    const float* ad2   = (const float*)d_in[11];
    const float* b2    = (const float*)d_in[12];
    const float* ow    = (const float*)d_in[13];
    const float* ob    = (const float*)d_in[14];
    float* out = (float*)d_out;

    const int* src = ei;
    const int* dst = ei + EE;

    int gemm_blocks = (NN + 63) / 64;
    int node_blocks = (NN + 7) / 8;
    int edge_blocks = (EE + 255) / 256;

    k_zero<<<(NN + 255) / 256, 256>>>();
    k_count<<<edge_blocks, 256>>>(dst);
    k_scan<<<1, 1024>>>();
    k_fill<<<edge_blocks, 256>>>(src, dst);

    // input projection: g_h = x @ lin_w + lin_b
    k_gemm<<<gemm_blocks, 256>>>(x, 1, lin_w, lin_b, 1, 1, nullptr, nullptr, 0);

    // GAT layer 1 (alpha fused into gemm epilogue)
    k_gemm<<<gemm_blocks, 256>>>(nullptr, 0, w1, nullptr, 0, 0, as1, ad1, 1);
    k_agg<<<node_blocks, 256>>>(b1, batch, 0);

    // GAT layer 2
    k_gemm<<<gemm_blocks, 256>>>(nullptr, 0, w2, nullptr, 0, 0, as2, ad2, 1);
    k_agg<<<node_blocks, 256>>>(b2, batch, 1);   // pooling fused

    k_final<<<GG, 128>>>(ow, ob, out);
}